// round 7
// baseline (speedup 1.0000x reference)
#include <cuda_runtime.h>
#include <cuda_bf16.h>
#include <cstdint>

// out[n] = prod_f sigmoid(10*(x[n,f]*w[f] + b[f]))^(1/2)
//        = rsqrt( prod_f (1 + exp(-10*(x*w + b))) )
//        = rsqrt( prod_f (1 + 2^(c_f * x + d_f)) )
// with c_f = -10*w_f*log2(e), d_f = -10*b_f*log2(e).
//
// Persistent grid-stride kernel, double-buffered loads so every resident warp
// always has PAIRS_PER_WARP * 512B of reads in flight.

#define F 64
#define PAIRS_PER_WARP 4
#define THREADS 256
#define BLOCKS 740   // ~5 per SM on 148-SM GB300

__device__ __forceinline__ float ex2f(float x) {
    float r;
    asm("ex2.approx.f32 %0, %1;" : "=f"(r) : "f"(x));
    return r;
}

__device__ __forceinline__ float4 ldcs4(const float4* p) {
    float4 v;
    asm volatile("ld.global.cs.v4.f32 {%0,%1,%2,%3}, [%4];"
                 : "=f"(v.x), "=f"(v.y), "=f"(v.z), "=f"(v.w) : "l"(p));
    return v;
}

__global__ void __launch_bounds__(THREADS)
onetoone_kernel(const float4* __restrict__ x4,
                const float4* __restrict__ w4,
                const float4* __restrict__ b4,
                float* __restrict__ out,
                int total_pairs)   // total_pairs = n_rows / 2
{
    const int lane = threadIdx.x & 31;
    const int j    = lane & 15;   // which float4 within the row (16 x float4 = 64 floats)
    const int half = lane >> 4;   // which row of the pair
    const int gwarp  = (int)((blockIdx.x * (unsigned)blockDim.x + threadIdx.x) >> 5);
    const int nwarps = (int)((gridDim.x * (unsigned)blockDim.x) >> 5);

    // Per-lane folded coefficients (constant across all rows this lane touches)
    const float S = -10.0f * 1.4426950408889634f;   // -scale * log2(e)
    float4 wv = __ldg(&w4[j]);
    float4 bv = __ldg(&b4[j]);
    const float c0 = S * wv.x, c1 = S * wv.y, c2 = S * wv.z, c3 = S * wv.w;
    const float d0 = S * bv.x, d1 = S * bv.y, d2 = S * bv.z, d3 = S * bv.w;

    // tiles of PAIRS_PER_WARP pairs; grid-stride over tiles
    const int total_tiles = (total_pairs + PAIRS_PER_WARP - 1) / PAIRS_PER_WARP;
    const int lane_off = half * (F / 4) + j;   // float4 offset of this lane within a pair

    int tile = gwarp;
    if (tile >= total_tiles) return;

    float4 cur[PAIRS_PER_WARP];
    // prologue: load first tile
    {
        int base_pair = tile * PAIRS_PER_WARP;
#pragma unroll
        for (int i = 0; i < PAIRS_PER_WARP; i++) {
            int pair = base_pair + i;
            if (pair < total_pairs)
                cur[i] = ldcs4(&x4[pair * 2 * (F / 4) + lane_off]);
        }
    }

    while (true) {
        int next_tile = tile + nwarps;
        float4 nxt[PAIRS_PER_WARP];
        const bool have_next = (next_tile < total_tiles);
        if (have_next) {
            int nbase = next_tile * PAIRS_PER_WARP;
#pragma unroll
            for (int i = 0; i < PAIRS_PER_WARP; i++) {
                int pair = nbase + i;
                if (pair < total_pairs)
                    nxt[i] = ldcs4(&x4[pair * 2 * (F / 4) + lane_off]);
            }
        }

        // compute current tile (loads for next tile stay in flight underneath)
        int base_pair = tile * PAIRS_PER_WARP;
#pragma unroll
        for (int i = 0; i < PAIRS_PER_WARP; i++) {
            int pair = base_pair + i;
            if (pair < total_pairs) {
                float t0 = fmaf(c0, cur[i].x, d0);
                float t1 = fmaf(c1, cur[i].y, d1);
                float t2 = fmaf(c2, cur[i].z, d2);
                float t3 = fmaf(c3, cur[i].w, d3);

                // lane-local product of 4 terms (each in (1, ~2^10+1]; bounded ~2^40)
                float p = ((1.0f + ex2f(t0)) * (1.0f + ex2f(t1))) *
                          ((1.0f + ex2f(t2)) * (1.0f + ex2f(t3)));

                // product over 8 lanes (32 terms) — still far from fp32 overflow
                p *= __shfl_xor_sync(0xFFFFFFFFu, p, 1);
                p *= __shfl_xor_sync(0xFFFFFFFFu, p, 2);
                p *= __shfl_xor_sync(0xFFFFFFFFu, p, 4);

                // sqrt-domain BEFORE the last combine so the full 64-term product
                // (mean ~e^58, tail toward fp32 overflow) never materializes.
                float q = rsqrtf(p);
                q *= __shfl_xor_sync(0xFFFFFFFFu, q, 8);

                if (j == 0) out[pair * 2 + half] = q;
            }
        }

        if (!have_next) break;
        tile = next_tile;
#pragma unroll
        for (int i = 0; i < PAIRS_PER_WARP; i++) cur[i] = nxt[i];
    }
}

extern "C" void kernel_launch(void* const* d_in, const int* in_sizes, int n_in,
                              void* d_out, int out_size)
{
    const float* x = (const float*)d_in[0];
    const float* w = (const float*)d_in[1];
    const float* b = (const float*)d_in[2];
    float* out = (float*)d_out;

    int n_rows = in_sizes[0] / F;          // 2,097,152
    int total_pairs = (n_rows + 1) / 2;    // 1,048,576

    onetoone_kernel<<<BLOCKS, THREADS>>>((const float4*)x,
                                         (const float4*)w,
                                         (const float4*)b,
                                         out, total_pairs);
}